// round 5
// baseline (speedup 1.0000x reference)
#include <cuda_runtime.h>
#include <cstdint>

#define T_TOK 8192
#define IN_F  2048
#define OUT_F 2048
#define THRESH 6.0f

// ---------------- device scratch ----------------
__device__ int8_t   g_wq[(size_t)OUT_F * IN_F];   // 4 MB
__device__ float    g_wscale[OUT_F];
__device__ int8_t   g_xq[(size_t)T_TOK * IN_F];   // 16 MB
__device__ float    g_xscale[T_TOK];
__device__ unsigned g_colmax[IN_F];
__device__ int      g_outidx[IN_F];
__device__ int      g_nout;

// ---------------- prep kernels (unchanged from passing round-1) ----------------
__global__ void k_init() {
    int i = blockIdx.x * 256 + threadIdx.x;
    if (i < IN_F) g_colmax[i] = 0u;
    if (i == 0) g_nout = 0;
}

__global__ void k_colmax(const float* __restrict__ x) {
    int c = blockIdx.x * 256 + threadIdx.x;
    const float* p = x + (size_t)blockIdx.y * 256 * IN_F + c;
    float m = 0.f;
#pragma unroll 4
    for (int r = 0; r < 256; ++r) m = fmaxf(m, fabsf(p[(size_t)r * IN_F]));
    atomicMax(&g_colmax[c], __float_as_uint(m));
}

__device__ __forceinline__ float block_reduce_max(float v, float* sh) {
#pragma unroll
    for (int o = 16; o > 0; o >>= 1) v = fmaxf(v, __shfl_xor_sync(0xffffffffu, v, o));
    int w = threadIdx.x >> 5;
    if ((threadIdx.x & 31) == 0) sh[w] = v;
    __syncthreads();
    float r = sh[0];
#pragma unroll
    for (int i = 1; i < 8; ++i) r = fmaxf(r, sh[i]);
    return r;
}

__global__ void k_quantw(const float* __restrict__ w) {
    __shared__ float sh[8];
    int row = blockIdx.x;
    const float* wr = w + (size_t)row * IN_F;
    float v[8]; float m = 0.f;
#pragma unroll
    for (int i = 0; i < 8; ++i) { v[i] = wr[threadIdx.x + i * 256]; m = fmaxf(m, fabsf(v[i])); }
    float amax = fmaxf(block_reduce_max(m, sh), 1e-6f);
    float s = 127.0f / amax;
#pragma unroll
    for (int i = 0; i < 8; ++i) {
        float q = rintf(v[i] * s);
        q = fminf(fmaxf(q, -127.f), 127.f);
        g_wq[(size_t)row * IN_F + threadIdx.x + i * 256] = (int8_t)q;
    }
    if (threadIdx.x == 0) g_wscale[row] = amax / 127.0f;
}

__global__ void k_gather() {
    __shared__ int warp_cnt[8];
    __shared__ int base_s;
    int tid = threadIdx.x, lane = tid & 31, w = tid >> 5;
    if (tid == 0) base_s = 0;
    __syncthreads();
    for (int start = 0; start < IN_F; start += 256) {
        int c = start + tid;
        bool f = __uint_as_float(g_colmax[c]) > THRESH;
        unsigned msk = __ballot_sync(0xffffffffu, f);
        if (lane == 0) warp_cnt[w] = __popc(msk);
        __syncthreads();
        int prefix = base_s;
        for (int i = 0; i < w; ++i) prefix += warp_cnt[i];
        if (f) g_outidx[prefix + __popc(msk & ((1u << lane) - 1u))] = c;
        __syncthreads();
        if (tid == 0) {
            int tot = 0;
            for (int i = 0; i < 8; ++i) tot += warp_cnt[i];
            base_s += tot;
        }
        __syncthreads();
    }
    if (tid == 0) g_nout = base_s;
}

__global__ void k_quantx(const float* __restrict__ x) {
    __shared__ float sh[8];
    int t = blockIdx.x;
    const float* xr = x + (size_t)t * IN_F;
    float v[8]; float m = 0.f;
#pragma unroll
    for (int i = 0; i < 8; ++i) {
        int c = threadIdx.x + i * 256;
        float f = xr[c];
        if (__uint_as_float(g_colmax[c]) > THRESH) f = 0.f;
        v[i] = f;
        m = fmaxf(m, fabsf(f));
    }
    float amax = fmaxf(block_reduce_max(m, sh), 1e-6f);
    float s = 127.0f / amax;
#pragma unroll
    for (int i = 0; i < 8; ++i) {
        float q = rintf(v[i] * s);
        q = fminf(fmaxf(q, -127.f), 127.f);
        g_xq[(size_t)t * IN_F + threadIdx.x + i * 256] = (int8_t)q;
    }
    if (threadIdx.x == 0) g_xscale[t] = amax / 127.0f;
}

// ---------------- IMMA int8 GEMM (warp-level mma.sync, target-neutral) ----------------
// BM=BN=128, BK=64. 256 threads = 8 warps, warp grid 2(m)x4(n), warp tile 64x32.
// Each warp: 4 m-frags x 4 n-frags of m16n8k32, 2 k32 steps per BK tile.
// SMEM pitch 80B -> fragment LDS.32 hits all 32 banks exactly once (conflict-free).
#define PITCH 80
#define KTILES (IN_F / 64)   // 32

__device__ __forceinline__ void mma16832(int* c, const uint32_t* a, const uint32_t* b) {
    asm volatile("mma.sync.aligned.m16n8k32.row.col.s32.s8.s8.s32 "
                 "{%0,%1,%2,%3}, {%4,%5,%6,%7}, {%8,%9}, {%0,%1,%2,%3};"
                 : "+r"(c[0]), "+r"(c[1]), "+r"(c[2]), "+r"(c[3])
                 : "r"(a[0]), "r"(a[1]), "r"(a[2]), "r"(a[3]), "r"(b[0]), "r"(b[1]));
}

__global__ __launch_bounds__(256) void k_gemm(const float* __restrict__ x,
                                              const float* __restrict__ bias,
                                              float* __restrict__ out) {
    __shared__ union {
        struct { int8_t A[2][128 * PITCH]; int8_t B[2][128 * PITCH]; } g;  // 40 KB
        struct { float xo[128 * 17]; float wqo[128 * 17]; } e;             // 17 KB
    } smem;

    const int tid = threadIdx.x;
    const int wid = tid >> 5, lane = tid & 31;
    const int warp_m = wid & 1;        // 0..1 -> rows warp_m*64
    const int warp_n = wid >> 1;       // 0..3 -> cols warp_n*32
    const int qrow = lane >> 2;        // 0..7
    const int qcol = lane & 3;         // 0..3
    const int m_blk = blockIdx.y * 128;
    const int n_blk = blockIdx.x * 128;

    const int4* gA = reinterpret_cast<const int4*>(g_xq);  // row pitch 128 int4
    const int4* gB = reinterpret_cast<const int4*>(g_wq);

    // loader mapping: chunks c = tid and tid+256; row = c>>2 (0..127), q = c&3
    const int lrow = tid >> 2;     // 0..63
    const int lq = tid & 3;

    int acc[4][4][4];
#pragma unroll
    for (int mf = 0; mf < 4; ++mf)
#pragma unroll
        for (int nf = 0; nf < 4; ++nf)
#pragma unroll
            for (int k = 0; k < 4; ++k) acc[mf][nf][k] = 0;

    // preload tile 0
    int4 pa0 = gA[(size_t)(m_blk + lrow) * 128 + lq];
    int4 pa1 = gA[(size_t)(m_blk + lrow + 64) * 128 + lq];
    int4 pb0 = gB[(size_t)(n_blk + lrow) * 128 + lq];
    int4 pb1 = gB[(size_t)(n_blk + lrow + 64) * 128 + lq];
    *reinterpret_cast<int4*>(&smem.g.A[0][lrow * PITCH + lq * 16]) = pa0;
    *reinterpret_cast<int4*>(&smem.g.A[0][(lrow + 64) * PITCH + lq * 16]) = pa1;
    *reinterpret_cast<int4*>(&smem.g.B[0][lrow * PITCH + lq * 16]) = pb0;
    *reinterpret_cast<int4*>(&smem.g.B[0][(lrow + 64) * PITCH + lq * 16]) = pb1;

#pragma unroll 1
    for (int t = 0; t < KTILES; ++t) {
        __syncthreads();
        const int buf = t & 1;
        const bool more = (t + 1) < KTILES;
        if (more) {
            int off = (t + 1) * 4 + lq;
            pa0 = gA[(size_t)(m_blk + lrow) * 128 + off];
            pa1 = gA[(size_t)(m_blk + lrow + 64) * 128 + off];
            pb0 = gB[(size_t)(n_blk + lrow) * 128 + off];
            pb1 = gB[(size_t)(n_blk + lrow + 64) * 128 + off];
        }
        const int8_t* aS = smem.g.A[buf];
        const int8_t* bS = smem.g.B[buf];
#pragma unroll
        for (int kk = 0; kk < 2; ++kk) {
            uint32_t af[4][4], bf[4][2];
#pragma unroll
            for (int mf = 0; mf < 4; ++mf) {
                const int8_t* p = aS + (warp_m * 64 + mf * 16 + qrow) * PITCH + kk * 32 + qcol * 4;
                af[mf][0] = *reinterpret_cast<const uint32_t*>(p);
                af[mf][1] = *reinterpret_cast<const uint32_t*>(p + 8 * PITCH);
                af[mf][2] = *reinterpret_cast<const uint32_t*>(p + 16);
                af[mf][3] = *reinterpret_cast<const uint32_t*>(p + 8 * PITCH + 16);
            }
#pragma unroll
            for (int nf = 0; nf < 4; ++nf) {
                const int8_t* p = bS + (warp_n * 32 + nf * 8 + qrow) * PITCH + kk * 32 + qcol * 4;
                bf[nf][0] = *reinterpret_cast<const uint32_t*>(p);
                bf[nf][1] = *reinterpret_cast<const uint32_t*>(p + 16);
            }
#pragma unroll
            for (int mf = 0; mf < 4; ++mf)
#pragma unroll
                for (int nf = 0; nf < 4; ++nf)
                    mma16832(acc[mf][nf], af[mf], bf[nf]);
        }
        if (more) {
            const int nb = buf ^ 1;
            __syncthreads();
            *reinterpret_cast<int4*>(&smem.g.A[nb][lrow * PITCH + lq * 16]) = pa0;
            *reinterpret_cast<int4*>(&smem.g.A[nb][(lrow + 64) * PITCH + lq * 16]) = pa1;
            *reinterpret_cast<int4*>(&smem.g.B[nb][lrow * PITCH + lq * 16]) = pb0;
            *reinterpret_cast<int4*>(&smem.g.B[nb][(lrow + 64) * PITCH + lq * 16]) = pb1;
        }
    }

    // ---- dequant ----
    // c0,c1: row qrow, cols 2*qcol,+1 ; c2,c3: row qrow+8
    float facc[4][4][4];
    float xsv[4][2];
#pragma unroll
    for (int mf = 0; mf < 4; ++mf) {
#pragma unroll
        for (int h = 0; h < 2; ++h)
            xsv[mf][h] = g_xscale[m_blk + warp_m * 64 + mf * 16 + qrow + h * 8];
    }
#pragma unroll
    for (int mf = 0; mf < 4; ++mf)
#pragma unroll
        for (int nf = 0; nf < 4; ++nf)
#pragma unroll
            for (int k = 0; k < 4; ++k)
                facc[mf][nf][k] = xsv[mf][k >> 1] * (float)acc[mf][nf][k];

    // ---- fp outlier epilogue (rank-nout update), staged 16 cols at a time ----
    const int nout = g_nout;
    for (int base = 0; base < nout; base += 16) {
        __syncthreads();
        const int rem = nout - base;
        for (int idx = tid; idx < 128 * 16; idx += 256) {
            int r = idx >> 4, c = idx & 15;
            float xv = 0.f, wv = 0.f;
            if (c < rem) {
                int col = g_outidx[base + c];
                xv = x[(size_t)(m_blk + r) * IN_F + col];
                wv = (float)g_wq[(size_t)(n_blk + r) * IN_F + col];
            }
            smem.e.xo[r * 17 + c] = xv;
            smem.e.wqo[r * 17 + c] = wv;
        }
        __syncthreads();
#pragma unroll 1
        for (int oc = 0; oc < 16; ++oc) {
            float xv[4][2], wv[4][2];
#pragma unroll
            for (int mf = 0; mf < 4; ++mf)
#pragma unroll
                for (int h = 0; h < 2; ++h)
                    xv[mf][h] = smem.e.xo[(warp_m * 64 + mf * 16 + qrow + h * 8) * 17 + oc];
#pragma unroll
            for (int nf = 0; nf < 4; ++nf)
#pragma unroll
                for (int j = 0; j < 2; ++j)
                    wv[nf][j] = smem.e.wqo[(warp_n * 32 + nf * 8 + qcol * 2 + j) * 17 + oc];
#pragma unroll
            for (int mf = 0; mf < 4; ++mf)
#pragma unroll
                for (int nf = 0; nf < 4; ++nf)
#pragma unroll
                    for (int h = 0; h < 2; ++h)
#pragma unroll
                        for (int j = 0; j < 2; ++j)
                            facc[mf][nf][h * 2 + j] += xv[mf][h] * wv[nf][j];
        }
    }

    // ---- scale + bias + store (float2 per accumulator pair) ----
    float wsv[4][2], bv[4][2];
#pragma unroll
    for (int nf = 0; nf < 4; ++nf)
#pragma unroll
        for (int j = 0; j < 2; ++j) {
            int gn = n_blk + warp_n * 32 + nf * 8 + qcol * 2 + j;
            wsv[nf][j] = g_wscale[gn];
            bv[nf][j] = bias[gn];
        }
#pragma unroll
    for (int mf = 0; mf < 4; ++mf)
#pragma unroll
        for (int h = 0; h < 2; ++h) {
            size_t row = (size_t)(m_blk + warp_m * 64 + mf * 16 + qrow + h * 8);
#pragma unroll
            for (int nf = 0; nf < 4; ++nf) {
                int gn = n_blk + warp_n * 32 + nf * 8 + qcol * 2;
                float2 o;
                o.x = wsv[nf][0] * facc[mf][nf][h * 2] + bv[nf][0];
                o.y = wsv[nf][1] * facc[mf][nf][h * 2 + 1] + bv[nf][1];
                *reinterpret_cast<float2*>(&out[row * OUT_F + gn]) = o;
            }
        }
}

// ---------------- launch ----------------
extern "C" void kernel_launch(void* const* d_in, const int* in_sizes, int n_in,
                              void* d_out, int out_size) {
    const float* x    = (const float*)d_in[0];
    const float* w    = (const float*)d_in[1];
    const float* bias = (const float*)d_in[2];
    float* out = (float*)d_out;

    k_init<<<8, 256>>>();
    k_colmax<<<dim3(IN_F / 256, 32), 256>>>(x);
    k_quantw<<<OUT_F, 256>>>(w);
    k_gather<<<1, 256>>>();
    k_quantx<<<T_TOK, 256>>>(x);
    k_gemm<<<dim3(OUT_F / 128, T_TOK / 128), 256>>>(x, bias, out);
}

// round 8
// speedup vs baseline: 1.7274x; 1.7274x over previous
#include <cuda_runtime.h>
#include <cstdint>

#define T_TOK 8192
#define IN_F  2048
#define OUT_F 2048
#define THRESH 6.0f

// ---------------- device scratch ----------------
__device__ int8_t   g_wq[(size_t)OUT_F * IN_F];   // 4 MB
__device__ float    g_wscale[OUT_F];
__device__ int8_t   g_xq[(size_t)T_TOK * IN_F];   // 16 MB
__device__ float    g_xscale[T_TOK];
__device__ unsigned g_colmax[IN_F];
__device__ int      g_outidx[IN_F];
__device__ int      g_nout;

// ---------------- prep kernels (unchanged, proven passing) ----------------
__global__ void k_init() {
    int i = blockIdx.x * 256 + threadIdx.x;
    if (i < IN_F) g_colmax[i] = 0u;
    if (i == 0) g_nout = 0;
}

__global__ void k_colmax(const float* __restrict__ x) {
    int c = blockIdx.x * 256 + threadIdx.x;
    const float* p = x + (size_t)blockIdx.y * 256 * IN_F + c;
    float m = 0.f;
#pragma unroll 4
    for (int r = 0; r < 256; ++r) m = fmaxf(m, fabsf(p[(size_t)r * IN_F]));
    atomicMax(&g_colmax[c], __float_as_uint(m));
}

__device__ __forceinline__ float block_reduce_max(float v, float* sh) {
#pragma unroll
    for (int o = 16; o > 0; o >>= 1) v = fmaxf(v, __shfl_xor_sync(0xffffffffu, v, o));
    int w = threadIdx.x >> 5;
    if ((threadIdx.x & 31) == 0) sh[w] = v;
    __syncthreads();
    float r = sh[0];
#pragma unroll
    for (int i = 1; i < 8; ++i) r = fmaxf(r, sh[i]);
    return r;
}

__global__ void k_quantw(const float* __restrict__ w) {
    __shared__ float sh[8];
    int row = blockIdx.x;
    const float* wr = w + (size_t)row * IN_F;
    float v[8]; float m = 0.f;
#pragma unroll
    for (int i = 0; i < 8; ++i) { v[i] = wr[threadIdx.x + i * 256]; m = fmaxf(m, fabsf(v[i])); }
    float amax = fmaxf(block_reduce_max(m, sh), 1e-6f);
    float s = 127.0f / amax;
#pragma unroll
    for (int i = 0; i < 8; ++i) {
        float q = rintf(v[i] * s);
        q = fminf(fmaxf(q, -127.f), 127.f);
        g_wq[(size_t)row * IN_F + threadIdx.x + i * 256] = (int8_t)q;
    }
    if (threadIdx.x == 0) g_wscale[row] = amax / 127.0f;
}

__global__ void k_gather() {
    __shared__ int warp_cnt[8];
    __shared__ int base_s;
    int tid = threadIdx.x, lane = tid & 31, w = tid >> 5;
    if (tid == 0) base_s = 0;
    __syncthreads();
    for (int start = 0; start < IN_F; start += 256) {
        int c = start + tid;
        bool f = __uint_as_float(g_colmax[c]) > THRESH;
        unsigned msk = __ballot_sync(0xffffffffu, f);
        if (lane == 0) warp_cnt[w] = __popc(msk);
        __syncthreads();
        int prefix = base_s;
        for (int i = 0; i < w; ++i) prefix += warp_cnt[i];
        if (f) g_outidx[prefix + __popc(msk & ((1u << lane) - 1u))] = c;
        __syncthreads();
        if (tid == 0) {
            int tot = 0;
            for (int i = 0; i < 8; ++i) tot += warp_cnt[i];
            base_s += tot;
        }
        __syncthreads();
    }
    if (tid == 0) g_nout = base_s;
}

__global__ void k_quantx(const float* __restrict__ x) {
    __shared__ float sh[8];
    int t = blockIdx.x;
    const float* xr = x + (size_t)t * IN_F;
    float v[8]; float m = 0.f;
#pragma unroll
    for (int i = 0; i < 8; ++i) {
        int c = threadIdx.x + i * 256;
        float f = xr[c];
        if (__uint_as_float(g_colmax[c]) > THRESH) f = 0.f;
        v[i] = f;
        m = fmaxf(m, fabsf(f));
    }
    float amax = fmaxf(block_reduce_max(m, sh), 1e-6f);
    float s = 127.0f / amax;
#pragma unroll
    for (int i = 0; i < 8; ++i) {
        float q = rintf(v[i] * s);
        q = fminf(fmaxf(q, -127.f), 127.f);
        g_xq[(size_t)t * IN_F + threadIdx.x + i * 256] = (int8_t)q;
    }
    if (threadIdx.x == 0) g_xscale[t] = amax / 127.0f;
}

// ---------------- DP4A GEMM v2: cp.async double-buffer, BK=128, SW128 ----------------
// BM=BN=128, 256 threads (8 warps), 8x8 microtile, 2 CTAs/SM.
// SMEM: A[2][16KB] at 0, B[2][16KB] at 32768; epilogue reuses from 0.
#define NTILES 16     // 2048 / 128

__device__ __forceinline__ uint32_t swz128(uint32_t off) { return off ^ ((off >> 3) & 0x70); }

__device__ __forceinline__ uint32_t smem_u32(const void* p) {
    uint32_t a;
    asm("{ .reg .u64 t; cvta.to.shared.u64 t, %1; cvt.u32.u64 %0, t; }" : "=r"(a) : "l"(p));
    return a;
}
__device__ __forceinline__ void cpa16(uint32_t dst, const void* src) {
    asm volatile("cp.async.cg.shared.global [%0], [%1], 16;" :: "r"(dst), "l"(src));
}
#define CP_COMMIT() asm volatile("cp.async.commit_group;" ::: "memory")
#define CP_WAIT0()  asm volatile("cp.async.wait_group 0;" ::: "memory")

__device__ __forceinline__ int dp4(uint32_t a, uint32_t b, int c) {
    return __dp4a((int)a, (int)b, c);
}

__global__ __launch_bounds__(256, 2) void k_gemm(const float* __restrict__ x,
                                                 const float* __restrict__ bias,
                                                 float* __restrict__ out) {
    extern __shared__ char sm[];
    const uint32_t sbase = smem_u32(sm);
    const int tid = threadIdx.x;
    const int tx = tid & 15;          // n dir: cols tx + j*16
    const int ty = tid >> 4;          // m dir: rows ty*8 + i
    const int m_blk = blockIdx.y * 128;
    const int n_blk = blockIdx.x * 128;

    // loader mapping: rows (tid>>3) + i*32, chunk lq = tid&7 within the 128B row
    const int lrow = tid >> 3;        // 0..31
    const int lq = tid & 7;
    const uint32_t sto = swz128((uint32_t)(lrow * 128 + lq * 16));

    int acc[8][8];
#pragma unroll
    for (int i = 0; i < 8; ++i)
#pragma unroll
        for (int j = 0; j < 8; ++j) acc[i][j] = 0;

    // ---- preload tile 0 ----
    {
        const int8_t* ga = g_xq + (size_t)(m_blk + lrow) * IN_F + lq * 16;
        const int8_t* gb = g_wq + (size_t)(n_blk + lrow) * IN_F + lq * 16;
#pragma unroll
        for (int i = 0; i < 4; ++i) {
            cpa16(sbase + sto + i * (32 * 128),         ga + (size_t)i * 32 * IN_F);
            cpa16(sbase + 32768 + sto + i * (32 * 128), gb + (size_t)i * 32 * IN_F);
        }
        CP_COMMIT(); CP_WAIT0();
    }
    __syncthreads();

#pragma unroll 1
    for (int t = 0; t < NTILES; ++t) {
        const int buf = t & 1;
        const bool more = (t + 1) < NTILES;
        if (more) {
            const int nb = buf ^ 1;
            const size_t kof = (size_t)(t + 1) * 128 + lq * 16;
            const int8_t* ga = g_xq + (size_t)(m_blk + lrow) * IN_F + kof;
            const int8_t* gb = g_wq + (size_t)(n_blk + lrow) * IN_F + kof;
#pragma unroll
            for (int i = 0; i < 4; ++i) {
                cpa16(sbase + nb * 16384 + sto + i * (32 * 128),         ga + (size_t)i * 32 * IN_F);
                cpa16(sbase + 32768 + nb * 16384 + sto + i * (32 * 128), gb + (size_t)i * 32 * IN_F);
            }
            CP_COMMIT();
        }
        const char* aS = sm + buf * 16384;
        const char* bS = sm + 32768 + buf * 16384;
#pragma unroll
        for (int kk = 0; kk < 8; ++kk) {
            uint4 bf[8];
#pragma unroll
            for (int j = 0; j < 8; ++j)
                bf[j] = *reinterpret_cast<const uint4*>(bS + swz128((uint32_t)((tx + j * 16) * 128 + kk * 16)));
#pragma unroll
            for (int i = 0; i < 8; ++i) {
                uint4 a = *reinterpret_cast<const uint4*>(aS + swz128((uint32_t)((ty * 8 + i) * 128 + kk * 16)));
#pragma unroll
                for (int j = 0; j < 8; ++j) {
                    acc[i][j] = dp4(a.x, bf[j].x, acc[i][j]);
                    acc[i][j] = dp4(a.y, bf[j].y, acc[i][j]);
                    acc[i][j] = dp4(a.z, bf[j].z, acc[i][j]);
                    acc[i][j] = dp4(a.w, bf[j].w, acc[i][j]);
                }
            }
        }
        if (more) CP_WAIT0();
        __syncthreads();
    }

    // ---- dequant + fp outlier epilogue ----
    float xs[8], ws[8], bs[8];
#pragma unroll
    for (int i = 0; i < 8; ++i) xs[i] = g_xscale[m_blk + ty * 8 + i];
#pragma unroll
    for (int j = 0; j < 8; ++j) {
        int gn = n_blk + tx + j * 16;
        ws[j] = g_wscale[gn];
        bs[j] = bias[gn];
    }

    float facc[8][8];
#pragma unroll
    for (int i = 0; i < 8; ++i)
#pragma unroll
        for (int j = 0; j < 8; ++j) facc[i][j] = xs[i] * (float)acc[i][j];

    float* xo = reinterpret_cast<float*>(sm);            // [128][17]
    float* wo = reinterpret_cast<float*>(sm + 8704);     // [128][17]

    const int nout = g_nout;
    for (int base = 0; base < nout; base += 16) {
        const int rem = nout - base;
        for (int idx = tid; idx < 128 * 16; idx += 256) {
            int r = idx >> 4, c = idx & 15;
            float xv = 0.f, wv = 0.f;
            if (c < rem) {
                int col = g_outidx[base + c];
                xv = x[(size_t)(m_blk + r) * IN_F + col];
                wv = (float)g_wq[(size_t)(n_blk + r) * IN_F + col];
            }
            xo[r * 17 + c] = xv;
            wo[r * 17 + c] = wv;
        }
        __syncthreads();
#pragma unroll
        for (int c = 0; c < 16; ++c) {
            float xa[8], wb[8];
#pragma unroll
            for (int i = 0; i < 8; ++i) xa[i] = xo[(ty * 8 + i) * 17 + c];
#pragma unroll
            for (int j = 0; j < 8; ++j) wb[j] = wo[(tx + j * 16) * 17 + c];
#pragma unroll
            for (int i = 0; i < 8; ++i)
#pragma unroll
                for (int j = 0; j < 8; ++j) facc[i][j] += xa[i] * wb[j];
        }
        __syncthreads();
    }

#pragma unroll
    for (int i = 0; i < 8; ++i) {
        size_t gm = m_blk + ty * 8 + i;
#pragma unroll
        for (int j = 0; j < 8; ++j) {
            int gn = n_blk + tx + j * 16;
            out[gm * OUT_F + gn] = ws[j] * facc[i][j] + bs[j];
        }
    }
}

// ---------------- launch ----------------
extern "C" void kernel_launch(void* const* d_in, const int* in_sizes, int n_in,
                              void* d_out, int out_size) {
    const float* x    = (const float*)d_in[0];
    const float* w    = (const float*)d_in[1];
    const float* bias = (const float*)d_in[2];
    float* out = (float*)d_out;

    cudaFuncSetAttribute(k_gemm, cudaFuncAttributeMaxDynamicSharedMemorySize, 65536);

    k_init<<<8, 256>>>();
    k_colmax<<<dim3(IN_F / 256, 32), 256>>>(x);
    k_quantw<<<OUT_F, 256>>>(w);
    k_gather<<<1, 256>>>();
    k_quantx<<<T_TOK, 256>>>(x);
    k_gemm<<<dim3(OUT_F / 128, T_TOK / 128), 256, 65536>>>(x, bias, out);
}

// round 10
// speedup vs baseline: 1.7378x; 1.0061x over previous
#include <cuda_runtime.h>
#include <cstdint>

#define T_TOK 8192
#define IN_F  2048
#define OUT_F 2048
#define THRESH 6.0f
#define MAXOUT 64

// ---------------- device scratch ----------------
__device__ int8_t   g_wq[(size_t)OUT_F * IN_F];   // 4 MB
__device__ float    g_wscale[OUT_F];
__device__ int8_t   g_xq[(size_t)T_TOK * IN_F];   // 16 MB
__device__ float    g_xscale[T_TOK];
__device__ unsigned g_colmax[IN_F];
__device__ int      g_outidx[IN_F];
__device__ int      g_nout;
__device__ float    g_xout[(size_t)T_TOK * MAXOUT];   // 2 MB packed outlier x
__device__ float    g_wout[(size_t)OUT_F * MAXOUT];   // 512 KB packed outlier wq

// ---------------- prep kernels ----------------
__global__ void k_init() {
    int i = blockIdx.x * 256 + threadIdx.x;
    if (i < IN_F) g_colmax[i] = 0u;
    if (i == 0) g_nout = 0;
}

__global__ void k_colmax(const float* __restrict__ x) {
    int c = blockIdx.x * 256 + threadIdx.x;
    const float* p = x + (size_t)blockIdx.y * 256 * IN_F + c;
    float m = 0.f;
#pragma unroll 4
    for (int r = 0; r < 256; ++r) m = fmaxf(m, fabsf(p[(size_t)r * IN_F]));
    atomicMax(&g_colmax[c], __float_as_uint(m));
}

__device__ __forceinline__ float block_reduce_max(float v, float* sh) {
#pragma unroll
    for (int o = 16; o > 0; o >>= 1) v = fmaxf(v, __shfl_xor_sync(0xffffffffu, v, o));
    int w = threadIdx.x >> 5;
    if ((threadIdx.x & 31) == 0) sh[w] = v;
    __syncthreads();
    float r = sh[0];
#pragma unroll
    for (int i = 1; i < 8; ++i) r = fmaxf(r, sh[i]);
    return r;
}

__global__ void k_quantw(const float* __restrict__ w) {
    __shared__ float sh[8];
    int row = blockIdx.x;
    const float* wr = w + (size_t)row * IN_F;
    float v[8]; float m = 0.f;
#pragma unroll
    for (int i = 0; i < 8; ++i) { v[i] = wr[threadIdx.x + i * 256]; m = fmaxf(m, fabsf(v[i])); }
    float amax = fmaxf(block_reduce_max(m, sh), 1e-6f);
    float s = 127.0f / amax;
#pragma unroll
    for (int i = 0; i < 8; ++i) {
        float q = rintf(v[i] * s);
        q = fminf(fmaxf(q, -127.f), 127.f);
        g_wq[(size_t)row * IN_F + threadIdx.x + i * 256] = (int8_t)q;
    }
    if (threadIdx.x == 0) g_wscale[row] = amax / 127.0f;
}

// deterministic parallel gather: rank = #outliers at lower column index
__global__ void k_gather2() {
    int c = blockIdx.x * 256 + threadIdx.x;
    if (c >= IN_F) return;
    if (__uint_as_float(g_colmax[c]) > THRESH) {
        int r = 0;
        for (int k = 0; k < c; ++k)
            r += (__uint_as_float(g_colmax[k]) > THRESH) ? 1 : 0;
        g_outidx[r] = c;
        atomicAdd(&g_nout, 1);
    }
}

// pack outlier columns of x and wq into padded [.,64] arrays (zero-filled)
__global__ void k_pack(const float* __restrict__ x) {
    int idx = blockIdx.x * 256 + threadIdx.x;
    int nout = g_nout; if (nout > MAXOUT) nout = MAXOUT;
    if (idx < T_TOK * MAXOUT) {
        int t = idx >> 6, s = idx & 63;
        float v = 0.f;
        if (s < nout) v = x[(size_t)t * IN_F + g_outidx[s]];
        g_xout[idx] = v;
    } else {
        int j = idx - T_TOK * MAXOUT;
        int o = j >> 6, s = j & 63;
        float v = 0.f;
        if (s < nout) v = (float)g_wq[(size_t)o * IN_F + g_outidx[s]];
        g_wout[j] = v;
    }
}

__global__ void k_quantx(const float* __restrict__ x) {
    __shared__ float sh[8];
    int t = blockIdx.x;
    const float* xr = x + (size_t)t * IN_F;
    float v[8]; float m = 0.f;
#pragma unroll
    for (int i = 0; i < 8; ++i) {
        int c = threadIdx.x + i * 256;
        float f = xr[c];
        if (__uint_as_float(g_colmax[c]) > THRESH) f = 0.f;
        v[i] = f;
        m = fmaxf(m, fabsf(f));
    }
    float amax = fmaxf(block_reduce_max(m, sh), 1e-6f);
    float s = 127.0f / amax;
#pragma unroll
    for (int i = 0; i < 8; ++i) {
        float q = rintf(v[i] * s);
        q = fminf(fmaxf(q, -127.f), 127.f);
        g_xq[(size_t)t * IN_F + threadIdx.x + i * 256] = (int8_t)q;
    }
    if (threadIdx.x == 0) g_xscale[t] = amax / 127.0f;
}

// ---------------- DP4A GEMM: cp.async double-buffer, BK=128, SW128 ----------------
#define NTILES 16     // 2048 / 128

__device__ __forceinline__ uint32_t swz128(uint32_t off) { return off ^ ((off >> 3) & 0x70); }

__device__ __forceinline__ uint32_t smem_u32(const void* p) {
    uint32_t a;
    asm("{ .reg .u64 t; cvta.to.shared.u64 t, %1; cvt.u32.u64 %0, t; }" : "=r"(a) : "l"(p));
    return a;
}
__device__ __forceinline__ void cpa16(uint32_t dst, const void* src) {
    asm volatile("cp.async.cg.shared.global [%0], [%1], 16;" :: "r"(dst), "l"(src));
}
#define CP_COMMIT() asm volatile("cp.async.commit_group;" ::: "memory")
#define CP_WAIT0()  asm volatile("cp.async.wait_group 0;" ::: "memory")

__device__ __forceinline__ int dp4(uint32_t a, uint32_t b, int c) {
    return __dp4a((int)a, (int)b, c);
}

__global__ __launch_bounds__(256, 2) void k_gemm(const float* __restrict__ bias,
                                                 float* __restrict__ out) {
    extern __shared__ char sm[];
    const uint32_t sbase = smem_u32(sm);
    const int tid = threadIdx.x;
    const int tx = tid & 15;          // n dir: cols tx + j*16
    const int ty = tid >> 4;          // m dir: rows ty*8 + i
    const int m_blk = blockIdx.y * 128;
    const int n_blk = blockIdx.x * 128;

    const int lrow = tid >> 3;        // 0..31
    const int lq = tid & 7;
    const uint32_t sto = swz128((uint32_t)(lrow * 128 + lq * 16));

    int acc[8][8];
#pragma unroll
    for (int i = 0; i < 8; ++i)
#pragma unroll
        for (int j = 0; j < 8; ++j) acc[i][j] = 0;

    // ---- preload tile 0 ----
    {
        const int8_t* ga = g_xq + (size_t)(m_blk + lrow) * IN_F + lq * 16;
        const int8_t* gb = g_wq + (size_t)(n_blk + lrow) * IN_F + lq * 16;
#pragma unroll
        for (int i = 0; i < 4; ++i) {
            cpa16(sbase + sto + i * (32 * 128),         ga + (size_t)i * 32 * IN_F);
            cpa16(sbase + 32768 + sto + i * (32 * 128), gb + (size_t)i * 32 * IN_F);
        }
        CP_COMMIT(); CP_WAIT0();
    }
    __syncthreads();

#pragma unroll 1
    for (int t = 0; t < NTILES; ++t) {
        const int buf = t & 1;
        const bool more = (t + 1) < NTILES;
        if (more) {
            const int nb = buf ^ 1;
            const size_t kof = (size_t)(t + 1) * 128 + lq * 16;
            const int8_t* ga = g_xq + (size_t)(m_blk + lrow) * IN_F + kof;
            const int8_t* gb = g_wq + (size_t)(n_blk + lrow) * IN_F + kof;
#pragma unroll
            for (int i = 0; i < 4; ++i) {
                cpa16(sbase + nb * 16384 + sto + i * (32 * 128),         ga + (size_t)i * 32 * IN_F);
                cpa16(sbase + 32768 + nb * 16384 + sto + i * (32 * 128), gb + (size_t)i * 32 * IN_F);
            }
            CP_COMMIT();
        }
        const char* aS = sm + buf * 16384;
        const char* bS = sm + 32768 + buf * 16384;
#pragma unroll
        for (int kk = 0; kk < 8; ++kk) {
            uint4 bf[8];
#pragma unroll
            for (int j = 0; j < 8; ++j)
                bf[j] = *reinterpret_cast<const uint4*>(bS + swz128((uint32_t)((tx + j * 16) * 128 + kk * 16)));
#pragma unroll
            for (int i = 0; i < 8; ++i) {
                uint4 a = *reinterpret_cast<const uint4*>(aS + swz128((uint32_t)((ty * 8 + i) * 128 + kk * 16)));
#pragma unroll
                for (int j = 0; j < 8; ++j) {
                    acc[i][j] = dp4(a.x, bf[j].x, acc[i][j]);
                    acc[i][j] = dp4(a.y, bf[j].y, acc[i][j]);
                    acc[i][j] = dp4(a.z, bf[j].z, acc[i][j]);
                    acc[i][j] = dp4(a.w, bf[j].w, acc[i][j]);
                }
            }
        }
        if (more) CP_WAIT0();
        __syncthreads();
    }

    // ---- dequant + fp outlier epilogue ----
    float xs[8], ws[8], bs[8];
#pragma unroll
    for (int i = 0; i < 8; ++i) xs[i] = g_xscale[m_blk + ty * 8 + i];
#pragma unroll
    for (int j = 0; j < 8; ++j) {
        int gn = n_blk + tx + j * 16;
        ws[j] = g_wscale[gn];
        bs[j] = bias[gn];
    }

    float facc[8][8];
#pragma unroll
    for (int i = 0; i < 8; ++i)
#pragma unroll
        for (int j = 0; j < 8; ++j) facc[i][j] = xs[i] * (float)acc[i][j];

    float* xo = reinterpret_cast<float*>(sm);            // [128][17]
    float* wo = reinterpret_cast<float*>(sm + 8704);     // [128][17]

    int nout = g_nout; if (nout > MAXOUT) nout = MAXOUT;
    for (int base = 0; base < nout; base += 16) {
        // staging from packed arrays: coalesced 64B-segment reads, no branches
        for (int idx = tid; idx < 128 * 16; idx += 256) {
            int r = idx >> 4, c = idx & 15;
            xo[r * 17 + c] = g_xout[(size_t)(m_blk + r) * MAXOUT + base + c];
            wo[r * 17 + c] = g_wout[(size_t)(n_blk + r) * MAXOUT + base + c];
        }
        __syncthreads();
#pragma unroll
        for (int c = 0; c < 16; ++c) {
            float xa[8], wb[8];
#pragma unroll
            for (int i = 0; i < 8; ++i) xa[i] = xo[(ty * 8 + i) * 17 + c];
#pragma unroll
            for (int j = 0; j < 8; ++j) wb[j] = wo[(tx + j * 16) * 17 + c];
#pragma unroll
            for (int i = 0; i < 8; ++i)
#pragma unroll
                for (int j = 0; j < 8; ++j) facc[i][j] += xa[i] * wb[j];
        }
        __syncthreads();
    }

#pragma unroll
    for (int i = 0; i < 8; ++i) {
        size_t gm = m_blk + ty * 8 + i;
#pragma unroll
        for (int j = 0; j < 8; ++j) {
            int gn = n_blk + tx + j * 16;
            out[gm * OUT_F + gn] = ws[j] * facc[i][j] + bs[j];
        }
    }
}

// ---------------- launch ----------------
extern "C" void kernel_launch(void* const* d_in, const int* in_sizes, int n_in,
                              void* d_out, int out_size) {
    const float* x    = (const float*)d_in[0];
    const float* w    = (const float*)d_in[1];
    const float* bias = (const float*)d_in[2];
    float* out = (float*)d_out;

    cudaFuncSetAttribute(k_gemm, cudaFuncAttributeMaxDynamicSharedMemorySize, 65536);

    k_init<<<8, 256>>>();
    k_colmax<<<dim3(IN_F / 256, 32), 256>>>(x);
    k_quantw<<<OUT_F, 256>>>(w);
    k_gather2<<<8, 256>>>();
    k_pack<<<(T_TOK + OUT_F) * MAXOUT / 256, 256>>>(x);
    k_quantx<<<T_TOK, 256>>>(x);
    k_gemm<<<dim3(OUT_F / 128, T_TOK / 128), 256, 65536>>>(bias, out);
}